// round 3
// baseline (speedup 1.0000x reference)
#include <cuda_runtime.h>
#include <cuda_fp16.h>

#define N_NODES 4096
#define N_CHILD 16384
#define DEGREE  64
#define BATCH   128
#define NNZ     (N_NODES * DEGREE)

// Scratch: E_T[c][b] = exp(child_ll[b][c]) in fp16 (4 MB, L2-resident)
__device__ __half g_Eh[(size_t)N_CHILD * BATCH];

// ---------------------------------------------------------------------------
// Kernel 1: exp + transpose + fp16 convert.
// child_ll [B=128, C=16384] f32 row-major  ->  g_Eh [C, B] fp16.
// ---------------------------------------------------------------------------
__global__ void __launch_bounds__(256) exp_tr_kernel(
    const float* __restrict__ child_ll) {
    __shared__ float tile[64][65];
    const int c0 = blockIdx.x * 64;
    const int b0 = blockIdx.y * 64;

    const int q  = threadIdx.x & 15;   // float4 index along c
    const int r0 = threadIdx.x >> 4;   // row (b) 0..15
#pragma unroll
    for (int rr = 0; rr < 64; rr += 16) {
        const int r = r0 + rr;
        const float4 v = *reinterpret_cast<const float4*>(
            &child_ll[(size_t)(b0 + r) * N_CHILD + c0 + q * 4]);
        tile[q * 4 + 0][r] = v.x;
        tile[q * 4 + 1][r] = v.y;
        tile[q * 4 + 2][r] = v.z;
        tile[q * 4 + 3][r] = v.w;
    }
    __syncthreads();

    const int c = threadIdx.x >> 2;    // 0..63
    const int s = threadIdx.x & 3;     // 0..3
#pragma unroll
    for (int h = 0; h < 2; h++) {
        const int b = s * 8 + h * 32;
        __half2 hv[4];
#pragma unroll
        for (int j = 0; j < 4; j++) {
            const float f0 = __expf(tile[c][b + 2 * j]);
            const float f1 = __expf(tile[c][b + 2 * j + 1]);
            hv[j] = __floats2half2_rn(f0, f1);
        }
        *reinterpret_cast<uint4*>(&g_Eh[(size_t)(c0 + c) * BATCH + b0 + b]) =
            *reinterpret_cast<const uint4*>(hv);
    }
}

// ---------------------------------------------------------------------------
// Kernel 2: fused gather-reduce, 2 warps per node (32 edges each).
// Within a warp: lanes 0-15 do even local edges, lanes 16-31 odd; each lane
// loads uint4 = 8 batches (16B, LDG.128). shfl_xor(16) merges sides, smem
// merges the warp pair, then log + coalesced float4 output.
// ---------------------------------------------------------------------------
__global__ void __launch_bounds__(256, 6) sum_nodes_kernel(
    const float* __restrict__ log_w, const int* __restrict__ cols,
    float* __restrict__ out) {
    const int tid  = threadIdx.x;
    const int wid  = tid >> 5;             // 0..7
    const int lane = tid & 31;
    const int nib  = wid >> 1;             // node-in-block 0..3
    const int half = wid & 1;              // which 32-edge half
    const int node0 = blockIdx.x * 4;
    const int node  = node0 + nib;
    const int nbase = node * DEGREE;

    __shared__ float s_w[4][64];
    __shared__ int   s_c[4][64];
    __shared__ float s_p[4][128];          // partial sums from half-0 warp
    __shared__ float s_o[128][5];          // [batch][node-in-block], padded

    // Weight normalization (both warps of the pair compute; half==0 stages).
    const float w0 = __expf(log_w[nbase + lane]);
    const float w1 = __expf(log_w[nbase + 32 + lane]);
    float ssum = w0 + w1;
#pragma unroll
    for (int o = 16; o; o >>= 1) ssum += __shfl_xor_sync(0xffffffffu, ssum, o);
    const float inv = 1.0f / ssum;
    if (half == 0) {
        s_w[nib][lane]      = w0 * inv;
        s_w[nib][lane + 32] = w1 * inv;
        s_c[nib][lane]      = cols[nbase + lane];
        s_c[nib][lane + 32] = cols[nbase + 32 + lane];
    }
    __syncthreads();

    const int g    = lane & 15;            // batch-group: batches g*8..g*8+7
    const int side = lane >> 4;            // 0: even local edges, 1: odd
    const int eb   = half * 32 + side;

    float acc[8] = {0.f, 0.f, 0.f, 0.f, 0.f, 0.f, 0.f, 0.f};

#pragma unroll 4
    for (int j = 0; j < 16; j++) {
        const int   e = eb + 2 * j;
        const int   c = s_c[nib][e];
        const float w = s_w[nib][e];
        const uint4 p = *reinterpret_cast<const uint4*>(
            &g_Eh[(size_t)c * BATCH + g * 8]);
        float2 f;
        f = __half22float2(*reinterpret_cast<const __half2*>(&p.x));
        acc[0] = fmaf(w, f.x, acc[0]); acc[1] = fmaf(w, f.y, acc[1]);
        f = __half22float2(*reinterpret_cast<const __half2*>(&p.y));
        acc[2] = fmaf(w, f.x, acc[2]); acc[3] = fmaf(w, f.y, acc[3]);
        f = __half22float2(*reinterpret_cast<const __half2*>(&p.z));
        acc[4] = fmaf(w, f.x, acc[4]); acc[5] = fmaf(w, f.y, acc[5]);
        f = __half22float2(*reinterpret_cast<const __half2*>(&p.w));
        acc[6] = fmaf(w, f.x, acc[6]); acc[7] = fmaf(w, f.y, acc[7]);
    }

    // Merge even/odd sides within the warp.
#pragma unroll
    for (int k = 0; k < 8; k++)
        acc[k] += __shfl_xor_sync(0xffffffffu, acc[k], 16);

    // Merge the warp pair via smem; half-1 warp finishes with log.
    if (half == 0 && side == 0) {
#pragma unroll
        for (int k = 0; k < 8; k++) s_p[nib][g * 8 + k] = acc[k];
    }
    __syncthreads();
    if (half == 1 && side == 0) {
#pragma unroll
        for (int k = 0; k < 8; k++)
            s_o[g * 8 + k][nib] = __logf(s_p[nib][g * 8 + k] + acc[k]);
    }
    __syncthreads();

    // Coalesced output: thread b writes float4 -> out[b][node0..node0+3].
    if (tid < 128) {
        const float4 v = make_float4(s_o[tid][0], s_o[tid][1],
                                     s_o[tid][2], s_o[tid][3]);
        *reinterpret_cast<float4*>(&out[(size_t)tid * N_NODES + node0]) = v;
    }
}

// ---------------------------------------------------------------------------
extern "C" void kernel_launch(void* const* d_in, const int* in_sizes, int n_in,
                              void* d_out, int out_size) {
    const float* child_ll = (const float*)d_in[0];  // [128, 16384] f32
    const float* log_w    = (const float*)d_in[1];  // [262144] f32
    // d_in[2] = rows: structurally repeat(arange(4096), 64) — unused
    const int*   cols     = (const int*)d_in[3];    // [262144] i32
    float*       out      = (float*)d_out;          // [128, 4096] f32

    dim3 tg(N_CHILD / 64, BATCH / 64);              // (256, 2)
    exp_tr_kernel<<<tg, 256>>>(child_ll);
    sum_nodes_kernel<<<N_NODES / 4, 256>>>(log_w, cols, out);
}